// round 16
// baseline (speedup 1.0000x reference)
#include <cuda_runtime.h>
#include <cuda_fp16.h>
#include <cstdint>
#include <cstddef>

// ---------------- static problem shape ----------------
constexpr int BSZ = 2;
constexpr int NQ  = 21760;
constexpr int MR  = BSZ * NQ;      // 43520 rows
constexpr int D   = 256;
constexpr int NH  = 8;
constexpr int DH  = 32;
constexpr int NFUSED = 384;        // 256 offs + 128 attn logits

__device__ __constant__ int c_LW[4] = {128, 64, 32, 16};
__device__ __constant__ int c_LH[4] = {128, 64, 32, 16};
__device__ __constant__ int c_LS[4] = {0, 16384, 20480, 21504};

// ---------------- scratch (ALL __half globals 16B-aligned: cp.async-safe) ----------------
__device__ __align__(16) __half g_vth[(size_t)BSZ * NH * NQ * DH];  // v^T [b][h][pos][c] fp16
__device__ float  g_P [(size_t)MR * NFUSED];             // raw offs(256) + attn logits(128)
__device__ __align__(16) __half g_vh [(size_t)MR * D];   // value fp16
__device__ __align__(16) __half g_qh [(size_t)MR * D];   // query fp16
__device__ __align__(16) __half g_tmph[(size_t)MR * D];  // attention output fp16
__device__ __align__(16) __half g_WvT  [D * D];          // Wv^T    [n][k] fp16
__device__ __align__(16) __half g_WfT  [NFUSED * D];     // [Wo|Wa]^T [n][k] fp16
__device__ __align__(16) __half g_WoutT[D * D];          // Wout^T  [n][k] fp16
__device__ float  g_bf[NFUSED];                          // fused [bo | ba]

// ---------------- helpers ----------------
__device__ __forceinline__ void mma_f16_k8(float& c0, float& c1, float& c2, float& c3,
                                           uint32_t a0, uint32_t a1, uint32_t b0) {
    asm volatile(
        "mma.sync.aligned.m16n8k8.row.col.f32.f16.f16.f32 "
        "{%0,%1,%2,%3}, {%4,%5}, {%6}, {%0,%1,%2,%3};"
        : "+f"(c0), "+f"(c1), "+f"(c2), "+f"(c3)
        : "r"(a0), "r"(a1), "r"(b0));
}

__device__ __forceinline__ void cp16(void* smem_dst, const void* gsrc) {
    unsigned d = (unsigned)__cvta_generic_to_shared(smem_dst);
    asm volatile("cp.async.cg.shared.global [%0], [%1], 16;" :: "r"(d), "l"(gsrc));
}

// ---------------- fused fp32->fp16 convert: value + query, one launch ----------------
__global__ void cvt_half_kernel(const float* __restrict__ value, const float* __restrict__ query) {
    const int n4 = MR * D / 4;
    int idx = blockIdx.x * blockDim.x + threadIdx.x;
    const float* src;
    __half* dst;
    int k = idx;
    if (idx < n4) { src = value; dst = g_vh; }
    else if (idx < 2 * n4) { src = query; dst = g_qh; k = idx - n4; }
    else return;
    const float4 v = reinterpret_cast<const float4*>(src)[k];
    __half2 a = __floats2half2_rn(v.x, v.y);
    __half2 b = __floats2half2_rn(v.z, v.w);
    uint2 o;
    o.x = *reinterpret_cast<uint32_t*>(&a);
    o.y = *reinterpret_cast<uint32_t*>(&b);
    reinterpret_cast<uint2*>(dst)[k] = o;
}

// ---------------- pack: biases + all transposed fp16 weights ----------------
__global__ void pack_w_kernel(const float* __restrict__ Wo, const float* __restrict__ bo,
                              const float* __restrict__ Wa, const float* __restrict__ ba,
                              const float* __restrict__ Wv, const float* __restrict__ Wout) {
    int i = blockIdx.x * blockDim.x + threadIdx.x;
    if (i < NFUSED) g_bf[i] = (i < 256) ? bo[i] : ba[i - 256];
    if (i < 65536) {                     // WvT[n][k] = Wv[k][n]
        int n = i >> 8, k = i & 255;
        g_WvT[i] = __float2half(Wv[k * 256 + n]);
    }
    int j = i - 65536;
    if (j >= 0 && j < NFUSED * 256) {    // WfT[n][k]
        int n = j >> 8, k = j & 255;
        g_WfT[j] = __float2half((n < 256) ? Wo[k * 256 + n] : Wa[k * 128 + (n - 256)]);
    }
    int j2 = j - NFUSED * 256;
    if (j2 >= 0 && j2 < 65536) {         // WoutT[n][k] = Wout[k][n]
        int n = j2 >> 8, k = j2 & 255;
        g_WoutT[j2] = __float2half(Wout[k * 256 + n]);
    }
}

// ---------------- fp16 m16n8k8 GEMM core (R14-validated structure) ----------------
// Tile BM=128, BN=64, BK=16; 8 warps 4(M)x2(N); warp tile 32x32.
// A [m][k] fp16 smem stride 24; W^T [n][k] fp16 smem stride 24.

// merged mode0+mode1 (one launch, one tail):
//   blockIdx.y < 4 : mode 0: A=g_vh, W=g_WvT -> g_vth scatter (fp16)
//   blockIdx.y >= 4: mode 1: A=g_qh, W=g_WfT -> g_P row-major
__global__ __launch_bounds__(256)
void gemm01_tc(const float* __restrict__ bv)
{
    constexpr int K = D;
    const int mode = (blockIdx.y >= 4);
    const __half* A    = mode ? g_qh  : g_vh;
    const __half* Wt   = mode ? g_WfT : g_WvT;
    const float*  bias = mode ? g_bf  : bv;
    const int n0       = (mode ? ((int)blockIdx.y - 4) : (int)blockIdx.y) * 64;

    __shared__ __align__(16) __half As[3][128][24];
    __shared__ __align__(16) __half Bs[3][64][24];

    const int tid  = threadIdx.x;
    const int warp = tid >> 5;
    const int lane = tid & 31;
    const int wm   = (warp & 3) * 32;
    const int wn   = (warp >> 2) * 32;
    const int m0   = blockIdx.x * 128;

    const int lrow = tid >> 1;
    const int lseg = tid & 1;

    float c[2][4][4];
    #pragma unroll
    for (int mf = 0; mf < 2; ++mf)
        #pragma unroll
        for (int nf = 0; nf < 4; ++nf)
            #pragma unroll
            for (int i = 0; i < 4; ++i) c[mf][nf][i] = 0.f;

    auto load_stage = [&](int kt, int buf) {
        const int kk = kt * 16;
        cp16(&As[buf][lrow][lseg * 8], A + (size_t)(m0 + lrow) * K + kk + lseg * 8);
        if (tid < 128)
            cp16(&Bs[buf][lrow][lseg * 8], Wt + (size_t)(n0 + lrow) * K + kk + lseg * 8);
        asm volatile("cp.async.commit_group;" ::: "memory");
    };

    load_stage(0, 0);
    load_stage(1, 1);

    const int qr = lane >> 2;
    const int t2 = (lane & 3) * 2;

    for (int kt = 0; kt < 16; ++kt) {
        const int buf = kt % 3;
        if (kt < 15) {
            asm volatile("cp.async.wait_group 1;" ::: "memory");
        } else {
            asm volatile("cp.async.wait_group 0;" ::: "memory");
        }
        __syncthreads();

        #pragma unroll
        for (int kc = 0; kc < 16; kc += 8) {
            uint32_t a[2][2], b[4];
            #pragma unroll
            for (int mf = 0; mf < 2; ++mf) {
                const int r0 = wm + qr + mf * 16;
                a[mf][0] = *reinterpret_cast<const uint32_t*>(&As[buf][r0    ][kc + t2]);
                a[mf][1] = *reinterpret_cast<const uint32_t*>(&As[buf][r0 + 8][kc + t2]);
            }
            #pragma unroll
            for (int nf = 0; nf < 4; ++nf) {
                const int nn = wn + nf * 8 + qr;
                b[nf] = *reinterpret_cast<const uint32_t*>(&Bs[buf][nn][kc + t2]);
            }
            #pragma unroll
            for (int mf = 0; mf < 2; ++mf)
                #pragma unroll
                for (int nf = 0; nf < 4; ++nf)
                    mma_f16_k8(c[mf][nf][0], c[mf][nf][1], c[mf][nf][2], c[mf][nf][3],
                               a[mf][0], a[mf][1], b[nf]);
        }

        if (kt + 2 < 16) load_stage(kt + 2, (kt + 2) % 3);
    }

    // epilogue (C layout identical to validated k8 kernels)
    #pragma unroll
    for (int mf = 0; mf < 2; ++mf) {
        #pragma unroll
        for (int nf = 0; nf < 4; ++nf) {
            const int cb = n0 + wn + nf * 8 + 2 * (lane & 3);
            const float2 b2 = *reinterpret_cast<const float2*>(bias + cb);
            #pragma unroll
            for (int half_i = 0; half_i < 2; ++half_i) {
                const int row = m0 + wm + mf * 16 + (lane >> 2) + half_i * 8;
                const float v0 = c[mf][nf][half_i * 2 + 0] + b2.x;
                const float v1 = c[mf][nf][half_i * 2 + 1] + b2.y;
                if (mode == 0) {
                    const int bb  = row / NQ;
                    const int pos = row - bb * NQ;
                    const __half2 hv = __floats2half2_rn(v0, v1);
                    *reinterpret_cast<__half2*>(
                        g_vth + ((size_t)(bb * NH + (cb >> 5)) * NQ + pos) * DH + (cb & 31)) = hv;
                } else {
                    *reinterpret_cast<float2*>(g_P + (size_t)row * NFUSED + cb)
                        = make_float2(v0, v1);
                }
            }
        }
    }
}

// ---------------- mode2 fp16 GEMM: out = g_tmph @ Wout + bout + query (R14, passed) ----------------
__global__ __launch_bounds__(256)
void gemm2_tc(const float* __restrict__ biasin, const float* __restrict__ addin,
              float* __restrict__ Cout)
{
    constexpr int K = D;
    const __half* A  = g_tmph;
    const __half* Wt = g_WoutT;

    __shared__ __align__(16) __half As[3][128][24];
    __shared__ __align__(16) __half Bs[3][64][24];

    const int tid  = threadIdx.x;
    const int warp = tid >> 5;
    const int lane = tid & 31;
    const int wm   = (warp & 3) * 32;
    const int wn   = (warp >> 2) * 32;
    const int m0   = blockIdx.x * 128;
    const int n0   = blockIdx.y * 64;

    const int lrow = tid >> 1;
    const int lseg = tid & 1;

    float c[2][4][4];
    #pragma unroll
    for (int mf = 0; mf < 2; ++mf)
        #pragma unroll
        for (int nf = 0; nf < 4; ++nf)
            #pragma unroll
            for (int i = 0; i < 4; ++i) c[mf][nf][i] = 0.f;

    auto load_stage = [&](int kt, int buf) {
        const int kk = kt * 16;
        cp16(&As[buf][lrow][lseg * 8], A + (size_t)(m0 + lrow) * K + kk + lseg * 8);
        if (tid < 128)
            cp16(&Bs[buf][lrow][lseg * 8], Wt + (size_t)(n0 + lrow) * K + kk + lseg * 8);
        asm volatile("cp.async.commit_group;" ::: "memory");
    };

    load_stage(0, 0);
    load_stage(1, 1);

    const int qr = lane >> 2;
    const int t2 = (lane & 3) * 2;

    for (int kt = 0; kt < 16; ++kt) {
        const int buf = kt % 3;
        if (kt < 15) {
            asm volatile("cp.async.wait_group 1;" ::: "memory");
        } else {
            asm volatile("cp.async.wait_group 0;" ::: "memory");
        }
        __syncthreads();

        #pragma unroll
        for (int kc = 0; kc < 16; kc += 8) {
            uint32_t a[2][2], b[4];
            #pragma unroll
            for (int mf = 0; mf < 2; ++mf) {
                const int r0 = wm + qr + mf * 16;
                a[mf][0] = *reinterpret_cast<const uint32_t*>(&As[buf][r0    ][kc + t2]);
                a[mf][1] = *reinterpret_cast<const uint32_t*>(&As[buf][r0 + 8][kc + t2]);
            }
            #pragma unroll
            for (int nf = 0; nf < 4; ++nf) {
                const int nn = wn + nf * 8 + qr;
                b[nf] = *reinterpret_cast<const uint32_t*>(&Bs[buf][nn][kc + t2]);
            }
            #pragma unroll
            for (int mf = 0; mf < 2; ++mf)
                #pragma unroll
                for (int nf = 0; nf < 4; ++nf)
                    mma_f16_k8(c[mf][nf][0], c[mf][nf][1], c[mf][nf][2], c[mf][nf][3],
                               a[mf][0], a[mf][1], b[nf]);
        }

        if (kt + 2 < 16) load_stage(kt + 2, (kt + 2) % 3);
    }

    #pragma unroll
    for (int mf = 0; mf < 2; ++mf) {
        #pragma unroll
        for (int nf = 0; nf < 4; ++nf) {
            const int cb = n0 + wn + nf * 8 + 2 * (lane & 3);
            const float2 b2 = *reinterpret_cast<const float2*>(biasin + cb);
            #pragma unroll
            for (int half_i = 0; half_i < 2; ++half_i) {
                const int row = m0 + wm + mf * 16 + (lane >> 2) + half_i * 8;
                const float v0 = c[mf][nf][half_i * 2 + 0] + b2.x;
                const float v1 = c[mf][nf][half_i * 2 + 1] + b2.y;
                const float2 q2 = *reinterpret_cast<const float2*>(
                    addin + (size_t)row * D + cb);
                *reinterpret_cast<float2*>(Cout + (size_t)row * D + cb)
                    = make_float2(v0 + q2.x, v1 + q2.y);
            }
        }
    }
}

// ---------------- fused softmax + coords + bilinear gather (R14, passed) ----------------
__global__ __launch_bounds__(256, 8)
void sample_kernel(const float* __restrict__ refp) {
    const int gwarp = blockIdx.x * 8 + (threadIdx.x >> 5);
    const int lane  = threadIdx.x & 31;
    if (gwarp >= MR * NH) return;
    const int h  = gwarp & 7;
    const int bq = gwarp >> 3;
    const int b  = (bq >= NQ);

    const float* Prow = g_P + (size_t)bq * NFUSED;
    const int i  = lane & 15;          // point index (lanes 16-31 mirror)
    const int il = i >> 2;

    // softmax over the 16 logits of this head
    float lg = Prow[256 + h * 16 + i];
    float mx = lg;
    #pragma unroll
    for (int off = 8; off; off >>= 1)
        mx = fmaxf(mx, __shfl_xor_sync(0xffffffffu, mx, off));
    float e = __expf(lg - mx);
    float ssum = e;
    #pragma unroll
    for (int off = 8; off; off >>= 1)
        ssum += __shfl_xor_sync(0xffffffffu, ssum, off);
    const float wgt = e / ssum;

    // pixel coords for this lane's point
    const float2 off2 = *reinterpret_cast<const float2*>(Prow + h * 32 + i * 2);
    const float2 ref2 = *reinterpret_cast<const float2*>(refp + (size_t)bq * 8 + il * 2);
    const float px = ref2.x * (float)c_LW[il] + off2.x - 0.5f;
    const float py = ref2.y * (float)c_LH[il] + off2.y - 0.5f;

    const int pgrp = lane >> 3;       // which point of the level this group does
    const int cq   = (lane & 7) * 4;  // channel quad
    const __half* vb = g_vth + ((size_t)(b * NH + h) * NQ) * DH + cq;

    __half2 acc01 = __float2half2_rn(0.f);
    __half2 acc23 = __float2half2_rn(0.f);
    #pragma unroll
    for (int j = 0; j < 4; ++j) {     // j = level
        const int Wl = c_LW[j], Hl = c_LH[j], st = c_LS[j];
        const int p  = j * 4 + pgrp;
        const float sx = __shfl_sync(0xffffffffu, px,  p);
        const float sy = __shfl_sync(0xffffffffu, py,  p);
        const float sw = __shfl_sync(0xffffffffu, wgt, p);

        const float xf = floorf(sx), yf = floorf(sy);
        const int   x0 = (int)xf,    y0 = (int)yf;
        const float wx1 = sx - xf,   wy1 = sy - yf;
        const float wx0 = 1.f - wx1, wy0 = 1.f - wy1;
        const int x1 = x0 + 1, y1 = y0 + 1;
        const bool vx0 = (unsigned)x0 < (unsigned)Wl;
        const bool vx1 = (unsigned)x1 < (unsigned)Wl;
        const bool vy0 = (unsigned)y0 < (unsigned)Hl;
        const bool vy1 = (unsigned)y1 < (unsigned)Hl;

        const float swy0 = sw * wy0;
        const float swy1 = sw * wy1;
        const __half2 w00h = __float2half2_rn(swy0 * wx0);
        const __half2 w01h = __float2half2_rn(swy0 * wx1);
        const __half2 w10h = __float2half2_rn(swy1 * wx0);
        const __half2 w11h = __float2half2_rn(swy1 * wx1);

        uint2 u00 = make_uint2(0u, 0u), u01 = u00, u10 = u00, u11 = u00;
        const __half* r0 = vb + (size_t)(st + y0 * Wl) * DH;
        const __half* r1 = vb + (size_t)(st + y1 * Wl) * DH;
        if (vy0 && vx0) u00 = *reinterpret_cast<const uint2*>(r0 + (size_t)x0 * DH);
        if (vy0 && vx1) u01 = *reinterpret_cast<const uint2*>(r0 + (size_t)x1 * DH);
        if (vy1 && vx0) u10 = *reinterpret_cast<const uint2*>(r1 + (size_t)x0 * DH);
        if (vy1 && vx1) u11 = *reinterpret_cast<const uint2*>(r1 + (size_t)x1 * DH);

        acc01 = __hfma2(*reinterpret_cast<const __half2*>(&u00.x), w00h, acc01);
        acc23 = __hfma2(*reinterpret_cast<const __half2*>(&u00.y), w00h, acc23);
        acc01 = __hfma2(*reinterpret_cast<const __half2*>(&u01.x), w01h, acc01);
        acc23 = __hfma2(*reinterpret_cast<const __half2*>(&u01.y), w01h, acc23);
        acc01 = __hfma2(*reinterpret_cast<const __half2*>(&u10.x), w10h, acc01);
        acc23 = __hfma2(*reinterpret_cast<const __half2*>(&u10.y), w10h, acc23);
        acc01 = __hfma2(*reinterpret_cast<const __half2*>(&u11.x), w11h, acc01);
        acc23 = __hfma2(*reinterpret_cast<const __half2*>(&u11.y), w11h, acc23);
    }

    // reduce across the 4 point-groups (lanes xor 8, 16)
    #pragma unroll
    for (int off = 8; off <= 16; off <<= 1) {
        uint32_t s01 = __shfl_xor_sync(0xffffffffu, *reinterpret_cast<uint32_t*>(&acc01), off);
        uint32_t s23 = __shfl_xor_sync(0xffffffffu, *reinterpret_cast<uint32_t*>(&acc23), off);
        acc01 = __hadd2(acc01, *reinterpret_cast<const __half2*>(&s01));
        acc23 = __hadd2(acc23, *reinterpret_cast<const __half2*>(&s23));
    }
    if (lane < 8) {
        uint2 o;
        o.x = *reinterpret_cast<uint32_t*>(&acc01);
        o.y = *reinterpret_cast<uint32_t*>(&acc23);
        *reinterpret_cast<uint2*>(g_tmph + (size_t)bq * D + h * DH + cq) = o;
    }
}

// ---------------- launch ----------------
extern "C" void kernel_launch(void* const* d_in, const int* in_sizes, int n_in,
                              void* d_out, int out_size) {
    const float* query = (const float*)d_in[0];
    const float* value = (const float*)d_in[1];
    const float* refp  = (const float*)d_in[2];
    const float* Wv   = (const float*)d_in[5];
    const float* bv   = (const float*)d_in[6];
    const float* Wo   = (const float*)d_in[7];
    const float* bo   = (const float*)d_in[8];
    const float* Wa   = (const float*)d_in[9];
    const float* ba   = (const float*)d_in[10];
    const float* Wout = (const float*)d_in[11];
    const float* bout = (const float*)d_in[12];
    float* out = (float*)d_out;

    // weights -> transposed fp16 + fused biases
    pack_w_kernel<<<(65536 + NFUSED * 256 + 65536 + 255) / 256, 256>>>(Wo, bo, Wa, ba, Wv, Wout);

    // value+query -> fp16 (one launch)
    cvt_half_kernel<<<(2 * MR * D / 4 + 255) / 256, 256>>>(value, query);

    // merged value-GEMM (y<4) + query-GEMM (y>=4), fp16
    gemm01_tc<<<dim3(MR / 128, 4 + NFUSED / 64), 256>>>(bv);

    sample_kernel<<<MR * NH / 8, 256>>>(refp);

    gemm2_tc<<<dim3(MR / 128, 256 / 64), 256>>>(bout, query, out);
}

// round 17
// speedup vs baseline: 1.0270x; 1.0270x over previous
#include <cuda_runtime.h>
#include <cuda_fp16.h>
#include <cstdint>
#include <cstddef>

// ---------------- static problem shape ----------------
constexpr int BSZ = 2;
constexpr int NQ  = 21760;
constexpr int MR  = BSZ * NQ;      // 43520 rows
constexpr int D   = 256;
constexpr int NH  = 8;
constexpr int DH  = 32;
constexpr int NFUSED = 384;        // 256 offs + 128 attn logits

__device__ __constant__ int c_LW[4] = {128, 64, 32, 16};
__device__ __constant__ int c_LH[4] = {128, 64, 32, 16};
__device__ __constant__ int c_LS[4] = {0, 16384, 20480, 21504};

// ---------------- scratch (16B-aligned __half globals: cp.async-safe) ----------------
__device__ __align__(16) __half g_vth[(size_t)BSZ * NH * NQ * DH];  // v^T [b][h][pos][c] fp16
__device__ float  g_P [(size_t)MR * NFUSED];            // raw offs(256) + attn logits(128)
__device__ __align__(16) __half g_tmph[(size_t)MR * D]; // attention output fp16
__device__ float  g_Wf[D * NFUSED];                     // fused [Wo | Wa] fp32
__device__ __align__(16) __half g_WoutT[D * D];         // Wout^T [n][k] fp16
__device__ float  g_bf[NFUSED];                         // fused [bo | ba]

// ---------------- helpers ----------------
__device__ __forceinline__ void mma_tf32(float& c0, float& c1, float& c2, float& c3,
                                         uint32_t a0, uint32_t a1, uint32_t a2, uint32_t a3,
                                         uint32_t b0, uint32_t b1) {
    asm volatile(
        "mma.sync.aligned.m16n8k8.row.col.f32.tf32.tf32.f32 "
        "{%0,%1,%2,%3}, {%4,%5,%6,%7}, {%8,%9}, {%0,%1,%2,%3};"
        : "+f"(c0), "+f"(c1), "+f"(c2), "+f"(c3)
        : "r"(a0), "r"(a1), "r"(a2), "r"(a3), "r"(b0), "r"(b1));
}

__device__ __forceinline__ void mma_f16_k8(float& c0, float& c1, float& c2, float& c3,
                                           uint32_t a0, uint32_t a1, uint32_t b0) {
    asm volatile(
        "mma.sync.aligned.m16n8k8.row.col.f32.f16.f16.f32 "
        "{%0,%1,%2,%3}, {%4,%5}, {%6}, {%0,%1,%2,%3};"
        : "+f"(c0), "+f"(c1), "+f"(c2), "+f"(c3)
        : "r"(a0), "r"(a1), "r"(b0));
}

__device__ __forceinline__ void cp16(void* smem_dst, const void* gsrc) {
    unsigned d = (unsigned)__cvta_generic_to_shared(smem_dst);
    asm volatile("cp.async.cg.shared.global [%0], [%1], 16;" :: "r"(d), "l"(gsrc));
}

// ---------------- pack: fused fp32 [Wo|Wa] + biases + fp16 Wout^T ----------------
__global__ void pack_w_kernel(const float* __restrict__ Wo, const float* __restrict__ bo,
                              const float* __restrict__ Wa, const float* __restrict__ ba,
                              const float* __restrict__ Wout) {
    int i = blockIdx.x * blockDim.x + threadIdx.x;
    if (i < NFUSED) g_bf[i] = (i < 256) ? bo[i] : ba[i - 256];
    if (i < D * NFUSED) {
        int k = i / NFUSED, n = i % NFUSED;
        g_Wf[i] = (n < 256) ? Wo[k * 256 + n] : Wa[k * 128 + (n - 256)];
    }
    int j = i - D * NFUSED;
    if (j >= 0 && j < 65536) {           // WoutT[n][k] = Wout[k][n]
        int n = j >> 8, k = j & 255;
        g_WoutT[j] = __float2half(Wout[k * 256 + n]);
    }
}

// ---------------- merged mode0+mode1 tf32 GEMM (R12/R14, validated) ----------------
// blockIdx.y < 4:  mode 0: A=value, W=Wv,   N=256    -> g_vth scatter (fp16)
// blockIdx.y >= 4: mode 1: A=query, W=g_Wf, N=NFUSED -> g_P row-major
__global__ __launch_bounds__(256)
void gemm01_tc(const float* __restrict__ value, const float* __restrict__ query,
               const float* __restrict__ Wv, const float* __restrict__ bv)
{
    constexpr int K = D;
    const int mode = (blockIdx.y >= 4);
    const float* A    = mode ? query : value;
    const float* W    = mode ? g_Wf  : Wv;
    const float* bias = mode ? g_bf  : bv;
    const int N       = mode ? NFUSED : 256;
    const int n0      = (mode ? ((int)blockIdx.y - 4) : (int)blockIdx.y) * 64;

    __shared__ float As[3][128][20];   // [stage][m][k], stride 20 -> conflict-free
    __shared__ float Bs[3][16][72];    // [stage][k][n], stride 72 -> conflict-free

    const int tid  = threadIdx.x;
    const int warp = tid >> 5;
    const int lane = tid & 31;
    const int wm   = (warp & 3) * 32;
    const int wn   = (warp >> 2) * 32;
    const int m0   = blockIdx.x * 128;

    const int ar = tid >> 2;   // 0..63 (and +64)
    const int aq = tid & 3;
    const int br = tid >> 4;   // 0..15
    const int bc = tid & 15;

    float c[2][4][4];
    #pragma unroll
    for (int mf = 0; mf < 2; ++mf)
        #pragma unroll
        for (int nf = 0; nf < 4; ++nf)
            #pragma unroll
            for (int i = 0; i < 4; ++i) c[mf][nf][i] = 0.f;

    auto load_stage = [&](int kt, int buf) {
        const int kk = kt * 16;
        cp16(&As[buf][ar][aq * 4],      A + (size_t)(m0 + ar) * K + kk + aq * 4);
        cp16(&As[buf][ar + 64][aq * 4], A + (size_t)(m0 + ar + 64) * K + kk + aq * 4);
        cp16(&Bs[buf][br][bc * 4],      W + (size_t)(kk + br) * N + n0 + bc * 4);
        asm volatile("cp.async.commit_group;" ::: "memory");
    };

    load_stage(0, 0);
    load_stage(1, 1);

    for (int kt = 0; kt < 16; ++kt) {
        const int buf = kt % 3;
        if (kt < 15) {
            asm volatile("cp.async.wait_group 1;" ::: "memory");
        } else {
            asm volatile("cp.async.wait_group 0;" ::: "memory");
        }
        __syncthreads();

        #pragma unroll
        for (int kc = 0; kc < 16; kc += 8) {
            uint32_t a[2][4], b[4][2];
            const int arow = wm + (lane >> 2);
            const int acol = kc + (lane & 3);
            #pragma unroll
            for (int mf = 0; mf < 2; ++mf) {
                const int r0 = arow + mf * 16;
                a[mf][0] = __float_as_uint(As[buf][r0    ][acol    ]);
                a[mf][1] = __float_as_uint(As[buf][r0 + 8][acol    ]);
                a[mf][2] = __float_as_uint(As[buf][r0    ][acol + 4]);
                a[mf][3] = __float_as_uint(As[buf][r0 + 8][acol + 4]);
            }
            #pragma unroll
            for (int nf = 0; nf < 4; ++nf) {
                const int nn = wn + nf * 8 + (lane >> 2);
                b[nf][0] = __float_as_uint(Bs[buf][acol    ][nn]);
                b[nf][1] = __float_as_uint(Bs[buf][acol + 4][nn]);
            }
            #pragma unroll
            for (int mf = 0; mf < 2; ++mf)
                #pragma unroll
                for (int nf = 0; nf < 4; ++nf)
                    mma_tf32(c[mf][nf][0], c[mf][nf][1], c[mf][nf][2], c[mf][nf][3],
                             a[mf][0], a[mf][1], a[mf][2], a[mf][3],
                             b[nf][0], b[nf][1]);
        }

        if (kt + 2 < 16) load_stage(kt + 2, (kt + 2) % 3);
    }

    // epilogue
    #pragma unroll
    for (int mf = 0; mf < 2; ++mf) {
        #pragma unroll
        for (int nf = 0; nf < 4; ++nf) {
            const int cb = n0 + wn + nf * 8 + 2 * (lane & 3);
            const float2 b2 = *reinterpret_cast<const float2*>(bias + cb);
            #pragma unroll
            for (int half_i = 0; half_i < 2; ++half_i) {
                const int row = m0 + wm + mf * 16 + (lane >> 2) + half_i * 8;
                const float v0 = c[mf][nf][half_i * 2 + 0] + b2.x;
                const float v1 = c[mf][nf][half_i * 2 + 1] + b2.y;
                if (mode == 0) {
                    const int bb  = row / NQ;
                    const int pos = row - bb * NQ;
                    const __half2 hv = __floats2half2_rn(v0, v1);
                    *reinterpret_cast<__half2*>(
                        g_vth + ((size_t)(bb * NH + (cb >> 5)) * NQ + pos) * DH + (cb & 31)) = hv;
                } else {
                    *reinterpret_cast<float2*>(g_P + (size_t)row * NFUSED + cb)
                        = make_float2(v0, v1);
                }
            }
        }
    }
}

// ---------------- mode2 fp16 GEMM: out = g_tmph @ Wout + bout + query (R14, validated) ----------------
__global__ __launch_bounds__(256)
void gemm2_tc(const float* __restrict__ biasin, const float* __restrict__ addin,
              float* __restrict__ Cout)
{
    constexpr int K = D;
    const __half* A  = g_tmph;
    const __half* Wt = g_WoutT;

    __shared__ __align__(16) __half As[3][128][24];
    __shared__ __align__(16) __half Bs[3][64][24];

    const int tid  = threadIdx.x;
    const int warp = tid >> 5;
    const int lane = tid & 31;
    const int wm   = (warp & 3) * 32;
    const int wn   = (warp >> 2) * 32;
    const int m0   = blockIdx.x * 128;
    const int n0   = blockIdx.y * 64;

    const int lrow = tid >> 1;
    const int lseg = tid & 1;

    float c[2][4][4];
    #pragma unroll
    for (int mf = 0; mf < 2; ++mf)
        #pragma unroll
        for (int nf = 0; nf < 4; ++nf)
            #pragma unroll
            for (int i = 0; i < 4; ++i) c[mf][nf][i] = 0.f;

    auto load_stage = [&](int kt, int buf) {
        const int kk = kt * 16;
        cp16(&As[buf][lrow][lseg * 8], A + (size_t)(m0 + lrow) * K + kk + lseg * 8);
        if (tid < 128)
            cp16(&Bs[buf][lrow][lseg * 8], Wt + (size_t)(n0 + lrow) * K + kk + lseg * 8);
        asm volatile("cp.async.commit_group;" ::: "memory");
    };

    load_stage(0, 0);
    load_stage(1, 1);

    const int qr = lane >> 2;
    const int t2 = (lane & 3) * 2;

    for (int kt = 0; kt < 16; ++kt) {
        const int buf = kt % 3;
        if (kt < 15) {
            asm volatile("cp.async.wait_group 1;" ::: "memory");
        } else {
            asm volatile("cp.async.wait_group 0;" ::: "memory");
        }
        __syncthreads();

        #pragma unroll
        for (int kc = 0; kc < 16; kc += 8) {
            uint32_t a[2][2], b[4];
            #pragma unroll
            for (int mf = 0; mf < 2; ++mf) {
                const int r0 = wm + qr + mf * 16;
                a[mf][0] = *reinterpret_cast<const uint32_t*>(&As[buf][r0    ][kc + t2]);
                a[mf][1] = *reinterpret_cast<const uint32_t*>(&As[buf][r0 + 8][kc + t2]);
            }
            #pragma unroll
            for (int nf = 0; nf < 4; ++nf) {
                const int nn = wn + nf * 8 + qr;
                b[nf] = *reinterpret_cast<const uint32_t*>(&Bs[buf][nn][kc + t2]);
            }
            #pragma unroll
            for (int mf = 0; mf < 2; ++mf)
                #pragma unroll
                for (int nf = 0; nf < 4; ++nf)
                    mma_f16_k8(c[mf][nf][0], c[mf][nf][1], c[mf][nf][2], c[mf][nf][3],
                               a[mf][0], a[mf][1], b[nf]);
        }

        if (kt + 2 < 16) load_stage(kt + 2, (kt + 2) % 3);
    }

    #pragma unroll
    for (int mf = 0; mf < 2; ++mf) {
        #pragma unroll
        for (int nf = 0; nf < 4; ++nf) {
            const int cb = n0 + wn + nf * 8 + 2 * (lane & 3);
            const float2 b2 = *reinterpret_cast<const float2*>(biasin + cb);
            #pragma unroll
            for (int half_i = 0; half_i < 2; ++half_i) {
                const int row = m0 + wm + mf * 16 + (lane >> 2) + half_i * 8;
                const float v0 = c[mf][nf][half_i * 2 + 0] + b2.x;
                const float v1 = c[mf][nf][half_i * 2 + 1] + b2.y;
                const float2 q2 = *reinterpret_cast<const float2*>(
                    addin + (size_t)row * D + cb);
                *reinterpret_cast<float2*>(Cout + (size_t)row * D + cb)
                    = make_float2(v0 + q2.x, v1 + q2.y);
            }
        }
    }
}

// ---------------- fused softmax + coords + bilinear gather ----------------
// NEW stage-2: 8 point-groups of 4 lanes; lane covers 8 channels (uint4 fp16).
// Corner math amortized over 8 points per warp-instruction (was 4); LDG count
// halves (8 x LDG.128 vs 16 x LDG.64); level params per-lane via shifts.
__global__ __launch_bounds__(256, 6)
void sample_kernel(const float* __restrict__ refp) {
    const int gwarp = blockIdx.x * 8 + (threadIdx.x >> 5);
    const int lane  = threadIdx.x & 31;
    if (gwarp >= MR * NH) return;
    const int h  = gwarp & 7;
    const int bq = gwarp >> 3;
    const int b  = (bq >= NQ);

    const float* Prow = g_P + (size_t)bq * NFUSED;
    const int i  = lane & 15;          // point index (lanes 16-31 mirror)
    const int il = i >> 2;

    // softmax over the 16 logits of this head
    float lg = Prow[256 + h * 16 + i];
    float mx = lg;
    #pragma unroll
    for (int off = 8; off; off >>= 1)
        mx = fmaxf(mx, __shfl_xor_sync(0xffffffffu, mx, off));
    float e = __expf(lg - mx);
    float ssum = e;
    #pragma unroll
    for (int off = 8; off; off >>= 1)
        ssum += __shfl_xor_sync(0xffffffffu, ssum, off);
    const float wgt = e / ssum;

    // pixel coords for this lane's point
    const float2 off2 = *reinterpret_cast<const float2*>(Prow + h * 32 + i * 2);
    const float2 ref2 = *reinterpret_cast<const float2*>(refp + (size_t)bq * 8 + il * 2);
    const float px = ref2.x * (float)c_LW[il] + off2.x - 0.5f;
    const float py = ref2.y * (float)c_LH[il] + off2.y - 0.5f;

    const int grp = lane >> 2;        // point group 0..7
    const int cq  = (lane & 3) * 8;   // channel start (8 channels per lane)
    const int hi  = lane >> 4;        // level selector within iteration
    const __half* vb = g_vth + ((size_t)(b * NH + h) * NQ) * DH + cq;

    __half2 acc0 = __float2half2_rn(0.f), acc1 = acc0, acc2 = acc0, acc3 = acc0;
    #pragma unroll
    for (int j = 0; j < 2; ++j) {     // iteration: points j*8 .. j*8+7
        const int p = j * 8 + grp;
        const float sx = __shfl_sync(0xffffffffu, px,  p);
        const float sy = __shfl_sync(0xffffffffu, py,  p);
        const float sw = __shfl_sync(0xffffffffu, wgt, p);

        const int lvl = j * 2 + hi;               // level of point p
        const int Wl  = 128 >> lvl;               // square levels: Hl == Wl
        const int st  = (j == 0) ? (hi << 14) : (20480 + (hi << 10));

        const float xf = floorf(sx), yf = floorf(sy);
        const int   x0 = (int)xf,    y0 = (int)yf;
        const float wx1 = sx - xf,   wy1 = sy - yf;
        const float wx0 = 1.f - wx1, wy0 = 1.f - wy1;
        const int x1 = x0 + 1, y1 = y0 + 1;
        const bool vx0 = (unsigned)x0 < (unsigned)Wl;
        const bool vx1 = (unsigned)x1 < (unsigned)Wl;
        const bool vy0 = (unsigned)y0 < (unsigned)Wl;
        const bool vy1 = (unsigned)y1 < (unsigned)Wl;

        const float swy0 = sw * wy0;
        const float swy1 = sw * wy1;
        const __half2 w00h = __float2half2_rn(swy0 * wx0);
        const __half2 w01h = __float2half2_rn(swy0 * wx1);
        const __half2 w10h = __float2half2_rn(swy1 * wx0);
        const __half2 w11h = __float2half2_rn(swy1 * wx1);

        uint4 u00 = make_uint4(0u,0u,0u,0u), u01 = u00, u10 = u00, u11 = u00;
        const __half* r0 = vb + (size_t)(st + y0 * Wl) * DH;
        const __half* r1 = vb + (size_t)(st + y1 * Wl) * DH;
        if (vy0 && vx0) u00 = *reinterpret_cast<const uint4*>(r0 + (size_t)x0 * DH);
        if (vy0 && vx1) u01 = *reinterpret_cast<const uint4*>(r0 + (size_t)x1 * DH);
        if (vy1 && vx0) u10 = *reinterpret_cast<const uint4*>(r1 + (size_t)x0 * DH);
        if (vy1 && vx1) u11 = *reinterpret_cast<const uint4*>(r1 + (size_t)x1 * DH);

        acc0 = __hfma2(*reinterpret_cast<const __half2*>(&u00.x), w00h, acc0);
        acc1 = __hfma2(*reinterpret_cast<const __half2*>(&u00.y), w00h, acc1);
        acc2 = __hfma2(*reinterpret_cast<const __half2*>(&u00.z), w00h, acc2);
        acc3 = __hfma2(*reinterpret_cast<const __half2*>(&u00.w), w00h, acc3);
        acc0 = __hfma2(*reinterpret_cast<const __half2*>(&u01.x), w01h, acc0);
        acc1 = __hfma2(*reinterpret_cast<const __half2*>(&u01.y), w01h, acc1);
        acc2 = __hfma2(*reinterpret_cast<const __half2*>(&u01.z), w01h, acc2);
        acc3 = __hfma2(*reinterpret_cast<const __half2*>(&u01.w), w01h, acc3);
        acc0 = __hfma2(*reinterpret_cast<const __half2*>(&u10.x), w10h, acc0);
        acc1 = __hfma2(*reinterpret_cast<const __half2*>(&u10.y), w10h, acc1);
        acc2 = __hfma2(*reinterpret_cast<const __half2*>(&u10.z), w10h, acc2);
        acc3 = __hfma2(*reinterpret_cast<const __half2*>(&u10.w), w10h, acc3);
        acc0 = __hfma2(*reinterpret_cast<const __half2*>(&u11.x), w11h, acc0);
        acc1 = __hfma2(*reinterpret_cast<const __half2*>(&u11.y), w11h, acc1);
        acc2 = __hfma2(*reinterpret_cast<const __half2*>(&u11.z), w11h, acc2);
        acc3 = __hfma2(*reinterpret_cast<const __half2*>(&u11.w), w11h, acc3);
    }

    // reduce across the 8 point-groups (lanes xor 4, 8, 16)
    #pragma unroll
    for (int off = 4; off <= 16; off <<= 1) {
        uint32_t s0 = __shfl_xor_sync(0xffffffffu, *reinterpret_cast<uint32_t*>(&acc0), off);
        uint32_t s1 = __shfl_xor_sync(0xffffffffu, *reinterpret_cast<uint32_t*>(&acc1), off);
        uint32_t s2 = __shfl_xor_sync(0xffffffffu, *reinterpret_cast<uint32_t*>(&acc2), off);
        uint32_t s3 = __shfl_xor_sync(0xffffffffu, *reinterpret_cast<uint32_t*>(&acc3), off);
        acc0 = __hadd2(acc0, *reinterpret_cast<const __half2*>(&s0));
        acc1 = __hadd2(acc1, *reinterpret_cast<const __half2*>(&s1));
        acc2 = __hadd2(acc2, *reinterpret_cast<const __half2*>(&s2));
        acc3 = __hadd2(acc3, *reinterpret_cast<const __half2*>(&s3));
    }
    if (lane < 4) {
        uint4 o;
        o.x = *reinterpret_cast<uint32_t*>(&acc0);
        o.y = *reinterpret_cast<uint32_t*>(&acc1);
        o.z = *reinterpret_cast<uint32_t*>(&acc2);
        o.w = *reinterpret_cast<uint32_t*>(&acc3);
        *reinterpret_cast<uint4*>(g_tmph + (size_t)bq * D + h * DH + cq) = o;
    }
}

// ---------------- launch ----------------
extern "C" void kernel_launch(void* const* d_in, const int* in_sizes, int n_in,
                              void* d_out, int out_size) {
    const float* query = (const float*)d_in[0];
    const float* value = (const float*)d_in[1];
    const float* refp  = (const float*)d_in[2];
    const float* Wv   = (const float*)d_in[5];
    const float* bv   = (const float*)d_in[6];
    const float* Wo   = (const float*)d_in[7];
    const float* bo   = (const float*)d_in[8];
    const float* Wa   = (const float*)d_in[9];
    const float* ba   = (const float*)d_in[10];
    const float* Wout = (const float*)d_in[11];
    const float* bout = (const float*)d_in[12];
    float* out = (float*)d_out;

    pack_w_kernel<<<(D * NFUSED + 65536 + 255) / 256, 256>>>(Wo, bo, Wa, ba, Wout);

    // merged value-GEMM (y<4) + query-GEMM (y>=4), tf32 (validated)
    gemm01_tc<<<dim3(MR / 128, 4 + NFUSED / 64), 256>>>(value, query, Wv, bv);

    sample_kernel<<<MR * NH / 8, 256>>>(refp);

    // fp16 gemm2 (validated): out = g_tmph @ Wout + bout + query
    gemm2_tc<<<dim3(MR / 128, 256 / 64), 256>>>(bout, query, out);
}